// round 15
// baseline (speedup 1.0000x reference)
#include <cuda_runtime.h>
#include <cuda_fp16.h>
#include <cstdint>
#include <cstddef>

#define BB 2
#define SS 2048
#define DD 768
#define HH 12
#define DK 64
#define DFF 3072
#define MM (BB*SS)                 // 4096
#define X2_ELEMS ((size_t)MM*DD)   // 3145728

// ---------------- scratch (static device globals; no allocation) -------------
__device__ __half g_Qh[(size_t)MM*DD];
__device__ __half g_Kh[(size_t)MM*DD];
__device__ __half g_Vh[(size_t)MM*DD];
__device__ __half g_Vth[(size_t)BB*HH*DK*SS];   // per-head V transposed [dk][seq]
__device__ __half g_ctxh[(size_t)MM*DD];
__device__ float  g_x1[(size_t)MM*DD];
__device__ __half g_x1h[(size_t)MM*DD];
__device__ float  g_t2[(size_t)MM*DD];
__device__ float  g_t2b[(size_t)MM*DD];
__device__ __half g_ffh[(size_t)MM*DFF];
__device__ __half g_xh[(size_t)MM*DD];
// transposed fp16 weights [N][K]
__device__ __half g_Wqh[(size_t)DD*DD];
__device__ __half g_Wkh[(size_t)DD*DD];
__device__ __half g_Wvh[(size_t)DD*DD];
__device__ __half g_Woh[(size_t)DD*DD];
__device__ __half g_W1h[(size_t)DFF*DD];
__device__ __half g_W2h[(size_t)DD*DFF];

// ---------------- helpers ----------------------------------------------------
__device__ __forceinline__ void mma16(float* c, const uint32_t* a, const uint32_t* b) {
    asm volatile(
        "mma.sync.aligned.m16n8k16.row.col.f32.f16.f16.f32 "
        "{%0,%1,%2,%3},{%4,%5,%6,%7},{%8,%9},{%0,%1,%2,%3};\n"
        : "+f"(c[0]), "+f"(c[1]), "+f"(c[2]), "+f"(c[3])
        : "r"(a[0]), "r"(a[1]), "r"(a[2]), "r"(a[3]), "r"(b[0]), "r"(b[1]));
}
__device__ __forceinline__ void cp16(uint32_t smem_addr, const void* gptr) {
    asm volatile("cp.async.cg.shared.global [%0], [%1], 16;\n"
                 :: "r"(smem_addr), "l"(gptr));
}
__device__ __forceinline__ void cp_commit() {
    asm volatile("cp.async.commit_group;\n" ::: "memory");
}
template<int N>
__device__ __forceinline__ void cp_wait() {
    asm volatile("cp.async.wait_group %0;\n" :: "n"(N) : "memory");
}
__device__ __forceinline__ uint32_t smem_u32(const void* p) {
    uint32_t a;
    asm("{ .reg .u64 t; cvta.to.shared.u64 t, %1; cvt.u32.u64 %0, t; }" : "=r"(a) : "l"(p));
    return a;
}
__device__ __forceinline__ uint32_t h2u(__half2 h) {
    return *reinterpret_cast<uint32_t*>(&h);
}
// logical u32 k-index -> physical (k-permute: (tg,tg+4) <-> (2tg,2tg+1))
__device__ __forceinline__ int kperm(int l) {
    int r = l & 7;
    int p = (r < 4) ? (2 * r) : (2 * (r - 4) + 1);
    return (l & ~7) | p;
}

// ---------------- merged prep: x->fp16 + 6 weight transposes -------------------
#define PREP_XBLK 3072
__global__ void prep_all(
    const float4* __restrict__ x,  __half2* __restrict__ xh,
    const float* __restrict__ wq, __half* __restrict__ wqh,
    const float* __restrict__ wk, __half* __restrict__ wkh,
    const float* __restrict__ wv, __half* __restrict__ wvh,
    const float* __restrict__ wo, __half* __restrict__ woh,
    const float* __restrict__ w1, __half* __restrict__ w1h,
    const float* __restrict__ w2, __half* __restrict__ w2h)
{
    int bid = blockIdx.x;
    int tid = threadIdx.x;
    if (bid < PREP_XBLK) {
        int i = bid * 256 + tid;
        float4 v = x[i];
        xh[i * 2]     = __floats2half2_rn(v.x, v.y);
        xh[i * 2 + 1] = __floats2half2_rn(v.z, v.w);
        return;
    }
    int t = bid - PREP_XBLK;
    const float* in; __half* out; int R, C;
    if      (t < 576)  { in = wq; out = wqh; R = DD;  C = DD;  }
    else if (t < 1152) { in = wk; out = wkh; R = DD;  C = DD;  t -= 576; }
    else if (t < 1728) { in = wv; out = wvh; R = DD;  C = DD;  t -= 1152; }
    else if (t < 2304) { in = wo; out = woh; R = DD;  C = DD;  t -= 1728; }
    else if (t < 4608) { in = w1; out = w1h; R = DD;  C = DFF; t -= 2304; }
    else               { in = w2; out = w2h; R = DFF; C = DD;  t -= 4608; }
    int nx = C / 32;
    int c0 = (t % nx) * 32, r0 = (t / nx) * 32;
    __shared__ float tt[32][33];
    int xx = tid & 31, yy = tid >> 5;    // 32 x 8
#pragma unroll
    for (int i = 0; i < 32; i += 8)
        tt[yy + i][xx] = in[(size_t)(r0 + yy + i) * C + c0 + xx];
    __syncthreads();
#pragma unroll
    for (int i = 0; i < 32; i += 8)
        out[(size_t)(c0 + yy + i) * R + r0 + xx] = __float2half_rn(tt[xx][yy + i]);
}

// ---------------- prep: per-head V [seq][dk] -> [dk][seq] fp16 -----------------
__global__ void v_transpose(const __half* __restrict__ Vh, __half* __restrict__ Vt)
{
    __shared__ __half t[64][72];
    int z = blockIdx.y;
    int b = z / HH, h = z % HH;
    int s0 = blockIdx.x * 64;
    const __half* src = Vh + (size_t)b * SS * DD + (size_t)h * DK;
    __half* dst = Vt + (size_t)z * DK * SS;
    int x = threadIdx.x, y = threadIdx.y;    // 64 x 4
#pragma unroll
    for (int i = 0; i < 64; i += 4)
        t[y + i][x] = src[(size_t)(s0 + y + i) * DD + x];
    __syncthreads();
#pragma unroll
    for (int i = 0; i < 64; i += 4)
        dst[(size_t)(y + i) * SS + s0 + x] = t[x][y + i];
}

// ---------------- fp16 dense GEMM:  C = A[M,K] @ Bt[N,K]^T (+ bias) -----------
// 128x128 tile, BK=64, 8 warps (warp 64x32), m16n8k16, k-permuted LDS.64.
// splitk: gridDim.z=2 computes K-halves; z selects output triple (partials).
#define DSTR 40   // u32 per 64-half row; half-warp banks 8g+2tg distinct
#define DENSE_SMEM (2 * 2 * 128 * DSTR * 4)   // 81920 B (A+B, 2 stages)
__global__ void __launch_bounds__(256, 2) dense_h(
    const __half* __restrict__ A,
    const __half* __restrict__ Bt0, const float* __restrict__ bias0,
    __half* __restrict__ H0, float* __restrict__ F0,
    const __half* __restrict__ Bt1, const float* __restrict__ bias1,
    __half* __restrict__ H1, float* __restrict__ F1,
    const __half* __restrict__ Bt2, const float* __restrict__ bias2,
    __half* __restrict__ H2, float* __restrict__ F2,
    int K, int Ntot, int relu, int splitk)
{
    extern __shared__ uint32_t dsm[];
    uint32_t* As = dsm;                    // 2 x 128 x DSTR
    uint32_t* Bs = dsm + 2 * 128 * DSTR;   // 2 x 128 x DSTR

    const int tid  = threadIdx.x;
    const int wid  = tid >> 5;
    const int lane = tid & 31;
    const int g    = lane >> 2;
    const int tg   = lane & 3;
    const int wm   = (wid >> 2) * 64;
    const int wn   = (wid & 3) * 32;

    const __half* Bt = Bt0; const float* bias = bias0;
    __half* H = H0; float* F = F0;
    if (blockIdx.z == 1) { Bt = Bt1; bias = bias1; H = H1; F = F1; }
    else if (blockIdx.z == 2) { Bt = Bt2; bias = bias2; H = H2; F = F2; }

    int keff = K, koff = 0;
    if (splitk) { keff = K >> 1; if (blockIdx.z == 1) koff = keff; }

    const int m0 = blockIdx.y * 128;
    const int n0 = blockIdx.x * 128;
    const __half* Ab = A + (size_t)m0 * K + koff;
    const __half* Bb = Bt + (size_t)n0 * K + koff;

    const uint32_t sA = smem_u32(As);
    const uint32_t sB = smem_u32(Bs);

    auto issue = [&](int ch, int st) {
        int k0 = ch * 64;
        uint32_t abuf = sA + st * (128 * DSTR) * 4;
        uint32_t bbuf = sB + st * (128 * DSTR) * 4;
#pragma unroll
        for (int i = 0; i < 4; i++) {
            int idx = tid + i * 256;
            int r = idx >> 3, c = idx & 7;
            cp16(abuf + (r * DSTR + c * 4) * 4, Ab + (size_t)r * K + k0 + c * 8);
            cp16(bbuf + (r * DSTR + c * 4) * 4, Bb + (size_t)r * K + k0 + c * 8);
        }
        cp_commit();
    };

    float c[4][4][4];
#pragma unroll
    for (int mi = 0; mi < 4; mi++)
#pragma unroll
        for (int j = 0; j < 4; j++)
#pragma unroll
            for (int r = 0; r < 4; r++) c[mi][j][r] = 0.f;

    const int nc = keff / 64;
    issue(0, 0);

    for (int kc = 0; kc < nc; kc++) {
        const int st = kc & 1;
        if (kc + 1 < nc) { issue(kc + 1, st ^ 1); cp_wait<1>(); }
        else             { cp_wait<0>(); }
        __syncthreads();

        const uint32_t* Ac = As + st * (128 * DSTR);
        const uint32_t* Bc = Bs + st * (128 * DSTR);
#pragma unroll
        for (int step = 0; step < 4; step++) {
            const int ko = step * 8;
            uint32_t af[4][4], bf[4][2];
#pragma unroll
            for (int mi = 0; mi < 4; mi++) {
                int m = wm + mi * 16 + g;
                uint2 p0 = *(const uint2*)&Ac[m * DSTR + ko + 2 * tg];
                uint2 p1 = *(const uint2*)&Ac[(m + 8) * DSTR + ko + 2 * tg];
                af[mi][0] = p0.x; af[mi][2] = p0.y;
                af[mi][1] = p1.x; af[mi][3] = p1.y;
            }
#pragma unroll
            for (int j = 0; j < 4; j++) {
                int n = wn + j * 8 + g;
                uint2 q = *(const uint2*)&Bc[n * DSTR + ko + 2 * tg];
                bf[j][0] = q.x; bf[j][1] = q.y;
            }
#pragma unroll
            for (int mi = 0; mi < 4; mi++)
#pragma unroll
                for (int j = 0; j < 4; j++) mma16(c[mi][j], af[mi], bf[j]);
        }
        __syncthreads();
    }

    // epilogue
#pragma unroll
    for (int mi = 0; mi < 4; mi++) {
        int r0 = m0 + wm + mi * 16 + g;
#pragma unroll
        for (int j = 0; j < 4; j++) {
            int col = n0 + wn + j * 8 + tg * 2;
            float2 bb = bias ? *(const float2*)(bias + col) : make_float2(0.f, 0.f);
            float v0 = c[mi][j][0] + bb.x;
            float v1 = c[mi][j][1] + bb.y;
            float v2 = c[mi][j][2] + bb.x;
            float v3 = c[mi][j][3] + bb.y;
            if (relu) {
                v0 = fmaxf(v0, 0.f); v1 = fmaxf(v1, 0.f);
                v2 = fmaxf(v2, 0.f); v3 = fmaxf(v3, 0.f);
            }
            if (H) {
                *(uint32_t*)(H + (size_t)r0 * Ntot + col)       = h2u(__floats2half2_rn(v0, v1));
                *(uint32_t*)(H + (size_t)(r0 + 8) * Ntot + col) = h2u(__floats2half2_rn(v2, v3));
            }
            if (F) {
                *(float2*)(F + (size_t)r0 * Ntot + col)       = make_float2(v0, v1);
                *(float2*)(F + (size_t)(r0 + 8) * Ntot + col) = make_float2(v2, v3);
            }
        }
    }
}

// ---------------- fused attention: phase0 sums, phase1 attn+ctx ---------------
// Block: 128 q-rows of one (b,h). Phase 0: stream K, accumulate row exp-sums in
// registers (no max shift; scores O(1)). Phase 1: re-stream K+V, recompute S
// (identical fetch/mma chain), write normalized attn once, ctx = P @ V.
#define HSTR 40
#define NC (SS/64)
#define APV_SMEM ((128*HSTR * 4) * 4 + 2048)
__global__ void __launch_bounds__(256) attn_pv_h(
    const __half* __restrict__ Q, const __half* __restrict__ Km,
    const __half* __restrict__ Vt,
    float* __restrict__ attn, __half* __restrict__ ctx)
{
    extern __shared__ uint32_t smu[];
    uint32_t* Qs = smu;                       // 128 x HSTR
    uint32_t* Ps = Qs + 128 * HSTR;           // 128 x HSTR (k-permuted layout)
    uint32_t* Ks = Ps + 128 * HSTR;           // 2 x 64 x HSTR
    uint32_t* Vs = Ks + 2 * 64 * HSTR;        // 2 x 64 x HSTR
    float* s_p = (float*)(Vs + 2 * 64 * HSTR);  // [128][2] warp partials
    float* s_i = s_p + 256;                     // [128] inv sums

    const int tid  = threadIdx.x;
    const int wid  = tid >> 5;
    const int lane = tid & 31;
    const int g    = lane >> 2;
    const int tg   = lane & 3;
    const int wm   = (wid >> 1) * 32;   // 4 row groups of 32
    const int wn   = (wid & 1) * 32;    // 2 col groups of 32

    const int z = blockIdx.y;
    const int b = z / HH, h = z % HH;
    const size_t base = (size_t)b * SS * DD + (size_t)h * DK;
    const int row0 = blockIdx.x * 128;
    float* Ab = attn + (size_t)z * SS * SS + (size_t)row0 * SS;
    const __half* Vz = Vt + (size_t)z * DK * SS;

    const uint32_t sQ = smem_u32(Qs);
    const uint32_t sK = smem_u32(Ks);
    const uint32_t sV = smem_u32(Vs);

    auto issueK = [&](int cc, int st) {
#pragma unroll
        for (int i = 0; i < 2; i++) {
            int idx = tid + i * 256;
            int r = idx >> 3, cch = idx & 7;
            cp16(sK + ((st * 64 + r) * HSTR + cch * 4) * 4,
                 Km + base + (size_t)(cc * 64 + r) * DD + cch * 8);
        }
        cp_commit();
    };
    auto issueKV = [&](int cc, int st) {
#pragma unroll
        for (int i = 0; i < 2; i++) {
            int idx = tid + i * 256;
            int r = idx >> 3, cch = idx & 7;
            cp16(sK + ((st * 64 + r) * HSTR + cch * 4) * 4,
                 Km + base + (size_t)(cc * 64 + r) * DD + cch * 8);
            cp16(sV + ((st * 64 + r) * HSTR + cch * 4) * 4,
                 Vz + (size_t)r * SS + cc * 64 + cch * 8);
        }
        cp_commit();
    };

    // Q tile (once) + first K chunk in one group
#pragma unroll
    for (int i = 0; i < 4; i++) {
        int idx = tid + i * 256;
        int r = idx >> 3, cch = idx & 7;
        cp16(sQ + (r * HSTR + cch * 4) * 4, Q + base + (size_t)(row0 + r) * DD + cch * 8);
    }
    issueK(0, 0);

    // ================= phase 0: row exp-sums =================
    float sacc[2][2] = {{0.f, 0.f}, {0.f, 0.f}};

    for (int cc = 0; cc < NC; cc++) {
        const int st = cc & 1;
        if (cc + 1 < NC) { issueK(cc + 1, st ^ 1); cp_wait<1>(); }
        else             { cp_wait<0>(); }
        __syncthreads();

        const uint32_t* Kc = Ks + st * 64 * HSTR;
        float c[2][4][4];
#pragma unroll
        for (int mi = 0; mi < 2; mi++)
#pragma unroll
            for (int j = 0; j < 4; j++)
#pragma unroll
                for (int r = 0; r < 4; r++) c[mi][j][r] = 0.f;

#pragma unroll
        for (int step = 0; step < 4; step++) {
            const int ko = step * 8;
            uint32_t af[2][4], bf[4][2];
#pragma unroll
            for (int mi = 0; mi < 2; mi++) {
                int m = wm + mi * 16 + g;
                uint2 p0 = *(const uint2*)&Qs[m * HSTR + ko + 2 * tg];
                uint2 p1 = *(const uint2*)&Qs[(m + 8) * HSTR + ko + 2 * tg];
                af[mi][0] = p0.x; af[mi][2] = p0.y;
                af[mi][1] = p1.x; af[mi][3] = p1.y;
            }
#pragma unroll
            for (int j = 0; j < 4; j++) {
                int n = wn + j * 8 + g;
                uint2 q = *(const uint2*)&Kc[n * HSTR + ko + 2 * tg];
                bf[j][0] = q.x; bf[j][1] = q.y;
            }
#pragma unroll
            for (int mi = 0; mi < 2; mi++)
#pragma unroll
                for (int j = 0; j < 4; j++) mma16(c[mi][j], af[mi], bf[j]);
        }

#pragma unroll
        for (int mi = 0; mi < 2; mi++)
#pragma unroll
            for (int half = 0; half < 2; half++) {
                float s = 0.f;
#pragma unroll
                for (int j = 0; j < 4; j++)
                    s += __expf(c[mi][j][half*2] * 0.125f)
                       + __expf(c[mi][j][half*2+1] * 0.125f);
                sacc[mi][half] += s;
            }
        __syncthreads();   // protect Ks[st] before reissue
    }

    // combine: tg lanes -> warp col-slice sum; 2 col-warps -> full row sum
#pragma unroll
    for (int mi = 0; mi < 2; mi++)
#pragma unroll
        for (int half = 0; half < 2; half++) {
            float s = sacc[mi][half];
            s += __shfl_xor_sync(0xffffffffu, s, 1);
            s += __shfl_xor_sync(0xffffffffu, s, 2);
            if (tg == 0)
                s_p[(wm + mi * 16 + g + half * 8) * 2 + (wid & 1)] = s;
        }
    __syncthreads();
    if (tid < 128)
        s_i[tid] = 1.0f / (s_p[tid * 2] + s_p[tid * 2 + 1]);

    // ================= phase 1: attn + ctx =================
    issueKV(0, 0);

    float acc[2][4][4];
#pragma unroll
    for (int mi = 0; mi < 2; mi++)
#pragma unroll
        for (int j = 0; j < 4; j++)
#pragma unroll
            for (int r = 0; r < 4; r++) acc[mi][j][r] = 0.f;

    for (int cc = 0; cc < NC; cc++) {
        const int st = cc & 1;
        if (cc + 1 < NC) { issueKV(cc + 1, st ^ 1); cp_wait<1>(); }
        else             { cp_wait<0>(); }
        __syncthreads();   // KV[st] ready; also publishes s_i on cc=0

        const uint32_t* Kc = Ks + st * 64 * HSTR;
        const uint32_t* Vc = Vs + st * 64 * HSTR;

        // ---- S = Q @ Kc^T (identical chain to phase 0) ----
        float c[2][4][4];
#pragma unroll
        for (int mi = 0; mi < 2; mi++)
#pragma unroll
            for (int j = 0; j < 4; j++)
#pragma unroll
                for (int r = 0; r < 4; r++) c[mi][j][r] = 0.f;

#pragma unroll
        for (int step = 0; step < 4; step++) {
            const int ko = step * 8;
            uint32_t af[2][4], bf[4][2];
#pragma unroll
            for (int mi = 0; mi < 2; mi++) {
                int m = wm + mi * 16 + g;
                uint2 p0 = *(const uint2*)&Qs[m * HSTR + ko + 2 * tg];
                uint2 p1 = *(const uint2*)&Qs[(m + 8) * HSTR + ko + 2 * tg];
                af[mi][0] = p0.x; af[mi][2] = p0.y;
                af[mi][1] = p1.x; af[mi][3] = p1.y;
            }
#pragma unroll
            for (int j = 0; j < 4; j++) {
                int n = wn + j * 8 + g;
                uint2 q = *(const uint2*)&Kc[n * HSTR + ko + 2 * tg];
                bf[j][0] = q.x; bf[j][1] = q.y;
            }
#pragma unroll
            for (int mi = 0; mi < 2; mi++)
#pragma unroll
                for (int j = 0; j < 4; j++) mma16(c[mi][j], af[mi], bf[j]);
        }

        // ---- normalize (no shift): write attn fp32, stage P (k-permuted) ----
#pragma unroll
        for (int mi = 0; mi < 2; mi++) {
#pragma unroll
            for (int half = 0; half < 2; half++) {
                int row = wm + mi * 16 + g + half * 8;
                float inv = s_i[row];
#pragma unroll
                for (int j = 0; j < 4; j++) {
                    float p0 = __expf(c[mi][j][half*2]   * 0.125f) * inv;
                    float p1 = __expf(c[mi][j][half*2+1] * 0.125f) * inv;
                    int col = wn + j * 8 + 2 * tg;
                    *(float2*)(Ab + (size_t)row * SS + cc * 64 + col) = make_float2(p0, p1);
                    Ps[row * HSTR + kperm(wn / 2 + 4 * j + tg)] = h2u(__floats2half2_rn(p0, p1));
                }
            }
        }
        __syncthreads();   // Ps complete

        // ---- ctx += P @ Vc^T: af permuted LDS.64 (pre-permuted Ps), bf straight ----
#pragma unroll
        for (int step = 0; step < 4; step++) {
            const int ko = step * 8;
            uint32_t af[2][4], bf[4][2];
#pragma unroll
            for (int mi = 0; mi < 2; mi++) {
                int m = wm + mi * 16 + g;
                uint2 p0 = *(const uint2*)&Ps[m * HSTR + ko + 2 * tg];
                uint2 p1 = *(const uint2*)&Ps[(m + 8) * HSTR + ko + 2 * tg];
                af[mi][0] = p0.x; af[mi][2] = p0.y;
                af[mi][1] = p1.x; af[mi][3] = p1.y;
            }
#pragma unroll
            for (int j = 0; j < 4; j++) {
                int n = wn + j * 8 + g;
                bf[j][0] = Vc[n * HSTR + ko + tg];
                bf[j][1] = Vc[n * HSTR + ko + tg + 4];
            }
#pragma unroll
            for (int mi = 0; mi < 2; mi++)
#pragma unroll
                for (int j = 0; j < 4; j++) mma16(acc[mi][j], af[mi], bf[j]);
        }
    }

    // ctx fp16 (feeds Wo GEMM)
#pragma unroll
    for (int mi = 0; mi < 2; mi++) {
        int r0 = row0 + wm + mi * 16 + g;
#pragma unroll
        for (int j = 0; j < 4; j++) {
            int col = wn + j * 8 + tg * 2;
            *(uint32_t*)(ctx + base + (size_t)r0 * DD + col) =
                h2u(__floats2half2_rn(acc[mi][j][0], acc[mi][j][1]));
            *(uint32_t*)(ctx + base + (size_t)(r0 + 8) * DD + col) =
                h2u(__floats2half2_rn(acc[mi][j][2], acc[mi][j][3]));
        }
    }
}

// ---------------- residual + two-partial sum + bias + layernorm ----------------
__global__ void add_ln2_kernel(const float* __restrict__ x,
                               const float* __restrict__ y1,
                               const float* __restrict__ y2,
                               const float* __restrict__ bias,
                               const float* __restrict__ g, const float* __restrict__ be,
                               float* __restrict__ po, __half* __restrict__ poh)
{
    size_t row = blockIdx.x;
    const float* px  = x  + row * DD;
    const float* py1 = y1 + row * DD;
    const float* py2 = y2 + row * DD;
    int t = threadIdx.x;
    __shared__ float red[256];

    float a0 = px[t]       + py1[t]       + py2[t]       + bias[t];
    float a1 = px[t + 256] + py1[t + 256] + py2[t + 256] + bias[t + 256];
    float a2 = px[t + 512] + py1[t + 512] + py2[t + 512] + bias[t + 512];

    red[t] = a0 + a1 + a2; __syncthreads();
    for (int s = 128; s > 0; s >>= 1) { if (t < s) red[t] += red[t + s]; __syncthreads(); }
    float mean = red[0] * (1.0f / DD); __syncthreads();

    float d0 = a0 - mean, d1 = a1 - mean, d2 = a2 - mean;
    red[t] = d0 * d0 + d1 * d1 + d2 * d2; __syncthreads();
    for (int s = 128; s > 0; s >>= 1) { if (t < s) red[t] += red[t + s]; __syncthreads(); }
    float rstd = rsqrtf(red[0] * (1.0f / DD) + 1e-5f);

    float o0 = d0 * rstd * g[t]       + be[t];
    float o1 = d1 * rstd * g[t + 256] + be[t + 256];
    float o2 = d2 * rstd * g[t + 512] + be[t + 512];
    po[row * DD + t] = o0; po[row * DD + t + 256] = o1; po[row * DD + t + 512] = o2;
    if (poh) {
        poh[row * DD + t]       = __float2half_rn(o0);
        poh[row * DD + t + 256] = __float2half_rn(o1);
        poh[row * DD + t + 512] = __float2half_rn(o2);
    }
}

// ---------------- launcher ----------------------------------------------------
extern "C" void kernel_launch(void* const* d_in, const int* in_sizes, int n_in,
                              void* d_out, int out_size)
{
    const float* x   = (const float*)d_in[0];
    const float* Wq  = (const float*)d_in[1];
    const float* bq  = (const float*)d_in[2];
    const float* Wk  = (const float*)d_in[3];
    const float* bk  = (const float*)d_in[4];
    const float* Wv  = (const float*)d_in[5];
    const float* bv  = (const float*)d_in[6];
    const float* Wo  = (const float*)d_in[7];
    const float* bo  = (const float*)d_in[8];
    const float* W1  = (const float*)d_in[9];
    const float* b1  = (const float*)d_in[10];
    const float* W2  = (const float*)d_in[11];
    const float* b2  = (const float*)d_in[12];
    const float* g1  = (const float*)d_in[13];
    const float* be1 = (const float*)d_in[14];
    const float* g2  = (const float*)d_in[15];
    const float* be2 = (const float*)d_in[16];

    float* out  = (float*)d_out;                 // x2: [2,2048,768]
    float* attn = out + X2_ELEMS;                // attn_weights: [2,12,2048,2048]

    __half *Qh, *Kh, *Vh, *Vth, *ctxh, *x1h, *ffh, *xh;
    __half *Wqh, *Wkh, *Wvh, *Woh, *W1h, *W2h;
    float *X1p, *T2p, *T2bp;
    cudaGetSymbolAddress((void**)&Qh,   g_Qh);
    cudaGetSymbolAddress((void**)&Kh,   g_Kh);
    cudaGetSymbolAddress((void**)&Vh,   g_Vh);
    cudaGetSymbolAddress((void**)&Vth,  g_Vth);
    cudaGetSymbolAddress((void**)&ctxh, g_ctxh);
    cudaGetSymbolAddress((void**)&x1h,  g_x1h);
    cudaGetSymbolAddress((void**)&ffh,  g_ffh);
    cudaGetSymbolAddress((void**)&xh,   g_xh);
    cudaGetSymbolAddress((void**)&Wqh,  g_Wqh);
    cudaGetSymbolAddress((void**)&Wkh,  g_Wkh);
    cudaGetSymbolAddress((void**)&Wvh,  g_Wvh);
    cudaGetSymbolAddress((void**)&Woh,  g_Woh);
    cudaGetSymbolAddress((void**)&W1h,  g_W1h);
    cudaGetSymbolAddress((void**)&W2h,  g_W2h);
    cudaGetSymbolAddress((void**)&X1p,  g_x1);
    cudaGetSymbolAddress((void**)&T2p,  g_t2);
    cudaGetSymbolAddress((void**)&T2bp, g_t2b);

    static int attr_set = 0;
    if (!attr_set) {
        cudaFuncSetAttribute(attn_pv_h, cudaFuncAttributeMaxDynamicSharedMemorySize,
                             APV_SMEM);
        cudaFuncSetAttribute(dense_h, cudaFuncAttributeMaxDynamicSharedMemorySize,
                             DENSE_SMEM);
        attr_set = 1;
    }

    // merged prep: x -> fp16 + all weight transposes (one launch)
    prep_all<<<PREP_XBLK + 6912, 256>>>(
        (const float4*)x, (__half2*)xh,
        Wq, Wqh, Wk, Wkh, Wv, Wvh, Wo, Woh, W1, W1h, W2, W2h);

    // merged Q/K/V projections (fp16 out)
    dense_h<<<dim3(DD/128, MM/128, 3), 256, DENSE_SMEM>>>(
        xh, Wqh, bq, Qh, nullptr, Wkh, bk, Kh, nullptr, Wvh, bv, Vh, nullptr,
        DD, DD, 0, 0);

    // per-head V transpose [seq][dk] -> [dk][seq]
    v_transpose<<<dim3(SS/64, BB*HH), dim3(64, 4)>>>(Vh, Vth);

    // fused attention: phase0 exp-sums (registers), phase1 attn write + ctx
    attn_pv_h<<<dim3(SS/128, BB*HH), 256, APV_SMEM>>>(Qh, Kh, Vth, attn, ctxh);

    // attn_out = ctx @ Wo (split-K=2 partials, bias deferred to LN)
    dense_h<<<dim3(DD/128, MM/128, 2), 256, DENSE_SMEM>>>(
        ctxh, Woh, nullptr, nullptr, T2p, Woh, nullptr, nullptr, T2bp,
        nullptr, nullptr, nullptr, nullptr, DD, DD, 0, 1);

    // x1 = LN(x + p1 + p2 + bo) -> fp32 + fp16
    add_ln2_kernel<<<MM, 256>>>(x, T2p, T2bp, bo, g1, be1, X1p, x1h);

    // ff = relu(x1 @ W1 + b1) fp16
    dense_h<<<dim3(DFF/128, MM/128, 1), 256, DENSE_SMEM>>>(
        x1h, W1h, b1, ffh, nullptr, nullptr, nullptr, nullptr, nullptr,
        nullptr, nullptr, nullptr, nullptr, DD, DFF, 1, 0);

    // ff2 = ff @ W2 (split-K=2 partials, bias deferred to LN)
    dense_h<<<dim3(DD/128, MM/128, 2), 256, DENSE_SMEM>>>(
        ffh, W2h, nullptr, nullptr, T2p, W2h, nullptr, nullptr, T2bp,
        nullptr, nullptr, nullptr, nullptr, DFF, DD, 0, 1);

    // x2 = LN(x1 + p1 + p2 + b2) -> output
    add_ln2_kernel<<<MM, 256>>>(X1p, T2p, T2bp, b2, g2, be2, out, nullptr);
}

// round 16
// speedup vs baseline: 1.0041x; 1.0041x over previous
#include <cuda_runtime.h>
#include <cuda_fp16.h>
#include <cstdint>
#include <cstddef>

#define BB 2
#define SS 2048
#define DD 768
#define HH 12
#define DK 64
#define DFF 3072
#define MM (BB*SS)                 // 4096
#define X2_ELEMS ((size_t)MM*DD)   // 3145728
#define NBLK 16                    // SS/128 col blocks per row
#define EXC 0.18033688011112042f   // 0.125 * log2(e)

// ---------------- scratch (static device globals; no allocation) -------------
__device__ __half g_Qh[(size_t)MM*DD];
__device__ __half g_Kh[(size_t)MM*DD];
__device__ __half g_Vh[(size_t)MM*DD];
__device__ __half g_Vth[(size_t)BB*HH*DK*SS];   // per-head V transposed [dk][seq]
__device__ __half g_ctxh[(size_t)MM*DD];
__device__ float  g_x1[(size_t)MM*DD];
__device__ __half g_x1h[(size_t)MM*DD];
__device__ float  g_t2[(size_t)MM*DD];
__device__ float  g_t2b[(size_t)MM*DD];
__device__ __half g_ffh[(size_t)MM*DFF];
__device__ __half g_xh[(size_t)MM*DD];
// transposed fp16 weights [N][K]
__device__ __half g_Wqh[(size_t)DD*DD];
__device__ __half g_Wkh[(size_t)DD*DD];
__device__ __half g_Wvh[(size_t)DD*DD];
__device__ __half g_Woh[(size_t)DD*DD];
__device__ __half g_W1h[(size_t)DFF*DD];
__device__ __half g_W2h[(size_t)DD*DFF];
// softmax partial sums / row inv-sums
__device__ float g_ps[(size_t)BB*HH*NBLK*SS];
__device__ float g_ri[(size_t)BB*HH*SS];

// ---------------- helpers ----------------------------------------------------
__device__ __forceinline__ void mma16(float* c, const uint32_t* a, const uint32_t* b) {
    asm volatile(
        "mma.sync.aligned.m16n8k16.row.col.f32.f16.f16.f32 "
        "{%0,%1,%2,%3},{%4,%5,%6,%7},{%8,%9},{%0,%1,%2,%3};\n"
        : "+f"(c[0]), "+f"(c[1]), "+f"(c[2]), "+f"(c[3])
        : "r"(a[0]), "r"(a[1]), "r"(a[2]), "r"(a[3]), "r"(b[0]), "r"(b[1]));
}
__device__ __forceinline__ float ex2(float x) {
    float r;
    asm("ex2.approx.f32 %0, %1;" : "=f"(r) : "f"(x));
    return r;
}
__device__ __forceinline__ void cp16(uint32_t smem_addr, const void* gptr) {
    asm volatile("cp.async.cg.shared.global [%0], [%1], 16;\n"
                 :: "r"(smem_addr), "l"(gptr));
}
__device__ __forceinline__ void cp_commit() {
    asm volatile("cp.async.commit_group;\n" ::: "memory");
}
template<int N>
__device__ __forceinline__ void cp_wait() {
    asm volatile("cp.async.wait_group %0;\n" :: "n"(N) : "memory");
}
__device__ __forceinline__ uint32_t smem_u32(const void* p) {
    uint32_t a;
    asm("{ .reg .u64 t; cvta.to.shared.u64 t, %1; cvt.u32.u64 %0, t; }" : "=r"(a) : "l"(p));
    return a;
}
__device__ __forceinline__ uint32_t h2u(__half2 h) {
    return *reinterpret_cast<uint32_t*>(&h);
}
__device__ __forceinline__ int kperm(int l) {
    int r = l & 7;
    int p = (r < 4) ? (2 * r) : (2 * (r - 4) + 1);
    return (l & ~7) | p;
}

// ---------------- merged prep: x->fp16 + 6 weight transposes -------------------
#define PREP_XBLK 3072
__global__ void prep_all(
    const float4* __restrict__ x,  __half2* __restrict__ xh,
    const float* __restrict__ wq, __half* __restrict__ wqh,
    const float* __restrict__ wk, __half* __restrict__ wkh,
    const float* __restrict__ wv, __half* __restrict__ wvh,
    const float* __restrict__ wo, __half* __restrict__ woh,
    const float* __restrict__ w1, __half* __restrict__ w1h,
    const float* __restrict__ w2, __half* __restrict__ w2h)
{
    int bid = blockIdx.x;
    int tid = threadIdx.x;
    if (bid < PREP_XBLK) {
        int i = bid * 256 + tid;
        float4 v = x[i];
        xh[i * 2]     = __floats2half2_rn(v.x, v.y);
        xh[i * 2 + 1] = __floats2half2_rn(v.z, v.w);
        return;
    }
    int t = bid - PREP_XBLK;
    const float* in; __half* out; int R, C;
    if      (t < 576)  { in = wq; out = wqh; R = DD;  C = DD;  }
    else if (t < 1152) { in = wk; out = wkh; R = DD;  C = DD;  t -= 576; }
    else if (t < 1728) { in = wv; out = wvh; R = DD;  C = DD;  t -= 1152; }
    else if (t < 2304) { in = wo; out = woh; R = DD;  C = DD;  t -= 1728; }
    else if (t < 4608) { in = w1; out = w1h; R = DD;  C = DFF; t -= 2304; }
    else               { in = w2; out = w2h; R = DFF; C = DD;  t -= 4608; }
    int nx = C / 32;
    int c0 = (t % nx) * 32, r0 = (t / nx) * 32;
    __shared__ float tt[32][33];
    int xx = tid & 31, yy = tid >> 5;    // 32 x 8
#pragma unroll
    for (int i = 0; i < 32; i += 8)
        tt[yy + i][xx] = in[(size_t)(r0 + yy + i) * C + c0 + xx];
    __syncthreads();
#pragma unroll
    for (int i = 0; i < 32; i += 8)
        out[(size_t)(c0 + yy + i) * R + r0 + xx] = __float2half_rn(tt[xx][yy + i]);
}

// ---------------- prep: per-head V [seq][dk] -> [dk][seq] fp16 -----------------
__global__ void v_transpose(const __half* __restrict__ Vh, __half* __restrict__ Vt)
{
    __shared__ __half t[64][72];
    int z = blockIdx.y;
    int b = z / HH, h = z % HH;
    int s0 = blockIdx.x * 64;
    const __half* src = Vh + (size_t)b * SS * DD + (size_t)h * DK;
    __half* dst = Vt + (size_t)z * DK * SS;
    int x = threadIdx.x, y = threadIdx.y;    // 64 x 4
#pragma unroll
    for (int i = 0; i < 64; i += 4)
        t[y + i][x] = src[(size_t)(s0 + y + i) * DD + x];
    __syncthreads();
#pragma unroll
    for (int i = 0; i < 64; i += 4)
        dst[(size_t)(y + i) * SS + s0 + x] = t[x][y + i];
}

// ---------------- fp16 dense GEMM:  C = A[M,K] @ Bt[N,K]^T (+ bias) -----------
#define DSTR 40
#define DENSE_SMEM (2 * 2 * 128 * DSTR * 4)   // 81920 B
__global__ void __launch_bounds__(256, 2) dense_h(
    const __half* __restrict__ A,
    const __half* __restrict__ Bt0, const float* __restrict__ bias0,
    __half* __restrict__ H0, float* __restrict__ F0,
    const __half* __restrict__ Bt1, const float* __restrict__ bias1,
    __half* __restrict__ H1, float* __restrict__ F1,
    const __half* __restrict__ Bt2, const float* __restrict__ bias2,
    __half* __restrict__ H2, float* __restrict__ F2,
    int K, int Ntot, int relu, int splitk)
{
    extern __shared__ uint32_t dsm[];
    uint32_t* As = dsm;
    uint32_t* Bs = dsm + 2 * 128 * DSTR;

    const int tid  = threadIdx.x;
    const int wid  = tid >> 5;
    const int lane = tid & 31;
    const int g    = lane >> 2;
    const int tg   = lane & 3;
    const int wm   = (wid >> 2) * 64;
    const int wn   = (wid & 3) * 32;

    const __half* Bt = Bt0; const float* bias = bias0;
    __half* H = H0; float* F = F0;
    if (blockIdx.z == 1) { Bt = Bt1; bias = bias1; H = H1; F = F1; }
    else if (blockIdx.z == 2) { Bt = Bt2; bias = bias2; H = H2; F = F2; }

    int keff = K, koff = 0;
    if (splitk) { keff = K >> 1; if (blockIdx.z == 1) koff = keff; }

    const int m0 = blockIdx.y * 128;
    const int n0 = blockIdx.x * 128;
    const __half* Ab = A + (size_t)m0 * K + koff;
    const __half* Bb = Bt + (size_t)n0 * K + koff;

    const uint32_t sA = smem_u32(As);
    const uint32_t sB = smem_u32(Bs);

    auto issue = [&](int ch, int st) {
        int k0 = ch * 64;
        uint32_t abuf = sA + st * (128 * DSTR) * 4;
        uint32_t bbuf = sB + st * (128 * DSTR) * 4;
#pragma unroll
        for (int i = 0; i < 4; i++) {
            int idx = tid + i * 256;
            int r = idx >> 3, c = idx & 7;
            cp16(abuf + (r * DSTR + c * 4) * 4, Ab + (size_t)r * K + k0 + c * 8);
            cp16(bbuf + (r * DSTR + c * 4) * 4, Bb + (size_t)r * K + k0 + c * 8);
        }
        cp_commit();
    };

    float c[4][4][4];
#pragma unroll
    for (int mi = 0; mi < 4; mi++)
#pragma unroll
        for (int j = 0; j < 4; j++)
#pragma unroll
            for (int r = 0; r < 4; r++) c[mi][j][r] = 0.f;

    const int nc = keff / 64;
    issue(0, 0);

    for (int kc = 0; kc < nc; kc++) {
        const int st = kc & 1;
        if (kc + 1 < nc) { issue(kc + 1, st ^ 1); cp_wait<1>(); }
        else             { cp_wait<0>(); }
        __syncthreads();

        const uint32_t* Ac = As + st * (128 * DSTR);
        const uint32_t* Bc = Bs + st * (128 * DSTR);
#pragma unroll
        for (int step = 0; step < 4; step++) {
            const int ko = step * 8;
            uint32_t af[4][4], bf[4][2];
#pragma unroll
            for (int mi = 0; mi < 4; mi++) {
                int m = wm + mi * 16 + g;
                uint2 p0 = *(const uint2*)&Ac[m * DSTR + ko + 2 * tg];
                uint2 p1 = *(const uint2*)&Ac[(m + 8) * DSTR + ko + 2 * tg];
                af[mi][0] = p0.x; af[mi][2] = p0.y;
                af[mi][1] = p1.x; af[mi][3] = p1.y;
            }
#pragma unroll
            for (int j = 0; j < 4; j++) {
                int n = wn + j * 8 + g;
                uint2 q = *(const uint2*)&Bc[n * DSTR + ko + 2 * tg];
                bf[j][0] = q.x; bf[j][1] = q.y;
            }
#pragma unroll
            for (int mi = 0; mi < 4; mi++)
#pragma unroll
                for (int j = 0; j < 4; j++) mma16(c[mi][j], af[mi], bf[j]);
        }
        __syncthreads();
    }

#pragma unroll
    for (int mi = 0; mi < 4; mi++) {
        int r0 = m0 + wm + mi * 16 + g;
#pragma unroll
        for (int j = 0; j < 4; j++) {
            int col = n0 + wn + j * 8 + tg * 2;
            float2 bb = bias ? *(const float2*)(bias + col) : make_float2(0.f, 0.f);
            float v0 = c[mi][j][0] + bb.x;
            float v1 = c[mi][j][1] + bb.y;
            float v2 = c[mi][j][2] + bb.x;
            float v3 = c[mi][j][3] + bb.y;
            if (relu) {
                v0 = fmaxf(v0, 0.f); v1 = fmaxf(v1, 0.f);
                v2 = fmaxf(v2, 0.f); v3 = fmaxf(v3, 0.f);
            }
            if (H) {
                *(uint32_t*)(H + (size_t)r0 * Ntot + col)       = h2u(__floats2half2_rn(v0, v1));
                *(uint32_t*)(H + (size_t)(r0 + 8) * Ntot + col) = h2u(__floats2half2_rn(v2, v3));
            }
            if (F) {
                *(float2*)(F + (size_t)r0 * Ntot + col)       = make_float2(v0, v1);
                *(float2*)(F + (size_t)(r0 + 8) * Ntot + col) = make_float2(v2, v3);
            }
        }
    }
}

// ---------------- stats: Q@K^T (fp16) -> per-block exp-sum partials ------------
#define HSTR 40
__global__ void __launch_bounds__(256, 2) stats_h(
    const __half* __restrict__ Q, const __half* __restrict__ Km,
    float* __restrict__ ps)
{
    __shared__ uint32_t Qs[128 * HSTR];
    __shared__ uint32_t Ks[128 * HSTR];
    __shared__ float sm_s[128][4];

    const int tid  = threadIdx.x;
    const int wid  = tid >> 5;
    const int lane = tid & 31;
    const int g    = lane >> 2;
    const int tg   = lane & 3;
    const int wm   = (wid >> 2) * 64;
    const int wn   = (wid & 3) * 32;

    const int z = blockIdx.z;
    const int b = z / HH, h = z % HH;
    const size_t base = (size_t)b * SS * DD + (size_t)h * DK;
    const int row0 = blockIdx.y * 128;
    const int col0 = blockIdx.x * 128;

    const uint32_t sQ = smem_u32(Qs);
    const uint32_t sK = smem_u32(Ks);

#pragma unroll
    for (int i = 0; i < 4; i++) {
        int idx = tid + i * 256;
        int r = idx >> 3, cch = idx & 7;
        cp16(sQ + (r * HSTR + cch * 4) * 4, Q  + base + (size_t)(row0 + r) * DD + cch * 8);
        cp16(sK + (r * HSTR + cch * 4) * 4, Km + base + (size_t)(col0 + r) * DD + cch * 8);
    }
    cp_commit();
    cp_wait<0>();
    __syncthreads();

    float c[4][4][4];
#pragma unroll
    for (int mi = 0; mi < 4; mi++)
#pragma unroll
        for (int j = 0; j < 4; j++)
#pragma unroll
            for (int r = 0; r < 4; r++) c[mi][j][r] = 0.f;

#pragma unroll
    for (int step = 0; step < 4; step++) {
        const int ko = step * 8;
        uint32_t af[4][4], bf[4][2];
#pragma unroll
        for (int mi = 0; mi < 4; mi++) {
            int m = wm + mi * 16 + g;
            uint2 p0 = *(const uint2*)&Qs[m * HSTR + ko + 2 * tg];
            uint2 p1 = *(const uint2*)&Qs[(m + 8) * HSTR + ko + 2 * tg];
            af[mi][0] = p0.x; af[mi][2] = p0.y;
            af[mi][1] = p1.x; af[mi][3] = p1.y;
        }
#pragma unroll
        for (int j = 0; j < 4; j++) {
            int n = wn + j * 8 + g;
            uint2 q = *(const uint2*)&Ks[n * HSTR + ko + 2 * tg];
            bf[j][0] = q.x; bf[j][1] = q.y;
        }
#pragma unroll
        for (int mi = 0; mi < 4; mi++)
#pragma unroll
            for (int j = 0; j < 4; j++) mma16(c[mi][j], af[mi], bf[j]);
    }

#pragma unroll
    for (int mi = 0; mi < 4; mi++) {
#pragma unroll
        for (int half = 0; half < 2; half++) {
            float s = 0.f;
#pragma unroll
            for (int j = 0; j < 4; j++)
                s += ex2(c[mi][j][half*2] * EXC) + ex2(c[mi][j][half*2+1] * EXC);
            s += __shfl_xor_sync(0xffffffffu, s, 1);
            s += __shfl_xor_sync(0xffffffffu, s, 2);
            if (tg == 0) {
                int row = wm + mi * 16 + g + half * 8;
                sm_s[row][wid & 3] = s;
            }
        }
    }
    __syncthreads();

    if (tid < 128) {
        float s = sm_s[tid][0] + sm_s[tid][1] + sm_s[tid][2] + sm_s[tid][3];
        ps[((size_t)z * NBLK + blockIdx.x) * SS + row0 + tid] = s;
    }
}

// ---------------- combine partial sums -> per-row 1/sum ------------------------
__global__ void rowstats(const float* __restrict__ ps, float* __restrict__ ri)
{
    int idx = blockIdx.x * blockDim.x + threadIdx.x;
    if (idx >= BB * HH * SS) return;
    int z = idx / SS, row = idx % SS;
    float s = 0.f;
#pragma unroll
    for (int blk = 0; blk < NBLK; blk++)
        s += ps[((size_t)z * NBLK + blk) * SS + row];
    ri[idx] = 1.0f / s;
}

// ---------------- attn_pv: col-split x2; recompute S, write attn, ctx partial --
#define NCH 16    // 1024/64 chunks per column half
#define APV_SMEM ((128*HSTR * 4) * 4 + 1024)
__global__ void __launch_bounds__(256) attn_pv_h(
    const __half* __restrict__ Q, const __half* __restrict__ Km,
    const __half* __restrict__ Vt,
    const float* __restrict__ ri,
    float* __restrict__ attn,
    float* __restrict__ ctxp0, float* __restrict__ ctxp1)
{
    extern __shared__ uint32_t smu[];
    uint32_t* Qs = smu;                       // 128 x HSTR
    uint32_t* Ps = Qs + 128 * HSTR;           // 128 x HSTR (k-permuted layout)
    uint32_t* Ks = Ps + 128 * HSTR;           // 2 x 64 x HSTR
    uint32_t* Vs = Ks + 2 * 64 * HSTR;        // 2 x 64 x HSTR
    float* s_i = (float*)(Vs + 2 * 64 * HSTR);

    const int tid  = threadIdx.x;
    const int wid  = tid >> 5;
    const int lane = tid & 31;
    const int g    = lane >> 2;
    const int tg   = lane & 3;
    const int wm   = (wid >> 1) * 32;
    const int wn   = (wid & 1) * 32;

    const int z = blockIdx.z;
    const int b = z / HH, h = z % HH;
    const size_t base = (size_t)b * SS * DD + (size_t)h * DK;
    const int row0 = blockIdx.x * 128;
    const int col0 = blockIdx.y * 1024;       // column half
    float* ctxp = blockIdx.y ? ctxp1 : ctxp0;
    float* Ab = attn + (size_t)z * SS * SS + (size_t)row0 * SS + col0;
    const __half* Vz = Vt + (size_t)z * DK * SS + col0;

    const uint32_t sQ = smem_u32(Qs);
    const uint32_t sK = smem_u32(Ks);
    const uint32_t sV = smem_u32(Vs);

    if (tid < 128)
        s_i[tid] = ri[(size_t)z * SS + row0 + tid];

    auto issueKV = [&](int cc, int st) {
#pragma unroll
        for (int i = 0; i < 2; i++) {
            int idx = tid + i * 256;
            int r = idx >> 3, cch = idx & 7;
            cp16(sK + ((st * 64 + r) * HSTR + cch * 4) * 4,
                 Km + base + (size_t)(col0 + cc * 64 + r) * DD + cch * 8);
            cp16(sV + ((st * 64 + r) * HSTR + cch * 4) * 4,
                 Vz + (size_t)r * SS + cc * 64 + cch * 8);
        }
        cp_commit();
    };

#pragma unroll
    for (int i = 0; i < 4; i++) {
        int idx = tid + i * 256;
        int r = idx >> 3, cch = idx & 7;
        cp16(sQ + (r * HSTR + cch * 4) * 4, Q + base + (size_t)(row0 + r) * DD + cch * 8);
    }
    issueKV(0, 0);

    float acc[2][4][4];
#pragma unroll
    for (int mi = 0; mi < 2; mi++)
#pragma unroll
        for (int j = 0; j < 4; j++)
#pragma unroll
            for (int r = 0; r < 4; r++) acc[mi][j][r] = 0.f;

    for (int cc = 0; cc < NCH; cc++) {
        const int st = cc & 1;
        if (cc + 1 < NCH) { issueKV(cc + 1, st ^ 1); cp_wait<1>(); }
        else              { cp_wait<0>(); }
        __syncthreads();

        const uint32_t* Kc = Ks + st * 64 * HSTR;
        const uint32_t* Vc = Vs + st * 64 * HSTR;

        // ---- S = Q @ Kc^T ----
        float c[2][4][4];
#pragma unroll
        for (int mi = 0; mi < 2; mi++)
#pragma unroll
            for (int j = 0; j < 4; j++)
#pragma unroll
                for (int r = 0; r < 4; r++) c[mi][j][r] = 0.f;

#pragma unroll
        for (int step = 0; step < 4; step++) {
            const int ko = step * 8;
            uint32_t af[2][4], bf[4][2];
#pragma unroll
            for (int mi = 0; mi < 2; mi++) {
                int m = wm + mi * 16 + g;
                uint2 p0 = *(const uint2*)&Qs[m * HSTR + ko + 2 * tg];
                uint2 p1 = *(const uint2*)&Qs[(m + 8) * HSTR + ko + 2 * tg];
                af[mi][0] = p0.x; af[mi][2] = p0.y;
                af[mi][1] = p1.x; af[mi][3] = p1.y;
            }
#pragma unroll
            for (int j = 0; j < 4; j++) {
                int n = wn + j * 8 + g;
                uint2 q = *(const uint2*)&Kc[n * HSTR + ko + 2 * tg];
                bf[j][0] = q.x; bf[j][1] = q.y;
            }
#pragma unroll
            for (int mi = 0; mi < 2; mi++)
#pragma unroll
                for (int j = 0; j < 4; j++) mma16(c[mi][j], af[mi], bf[j]);
        }

        // ---- normalize (no shift, ex2): write attn fp32, stage P (k-permuted) ----
#pragma unroll
        for (int mi = 0; mi < 2; mi++) {
#pragma unroll
            for (int half = 0; half < 2; half++) {
                int row = wm + mi * 16 + g + half * 8;
                float inv = s_i[row];
#pragma unroll
                for (int j = 0; j < 4; j++) {
                    float p0 = ex2(c[mi][j][half*2]   * EXC) * inv;
                    float p1 = ex2(c[mi][j][half*2+1] * EXC) * inv;
                    int col = wn + j * 8 + 2 * tg;
                    *(float2*)(Ab + (size_t)row * SS + cc * 64 + col) = make_float2(p0, p1);
                    Ps[row * HSTR + kperm(wn / 2 + 4 * j + tg)] = h2u(__floats2half2_rn(p0, p1));
                }
            }
        }
        __syncthreads();

        // ---- ctx += P @ Vc^T ----
#pragma unroll
        for (int step = 0; step < 4; step++) {
            const int ko = step * 8;
            uint32_t af[2][4], bf[4][2];
#pragma unroll
            for (int mi = 0; mi < 2; mi++) {
                int m = wm + mi * 16 + g;
                uint2 p0 = *(const uint2*)&Ps[m * HSTR + ko + 2 * tg];
                uint2 p1 = *(const uint2*)&Ps[(m + 8) * HSTR + ko + 2 * tg];
                af[mi][0] = p0.x; af[mi][2] = p0.y;
                af[mi][1] = p1.x; af[mi][3] = p1.y;
            }
#pragma unroll
            for (int j = 0; j < 4; j++) {
                int n = wn + j * 8 + g;
                bf[j][0] = Vc[n * HSTR + ko + tg];
                bf[j][1] = Vc[n * HSTR + ko + tg + 4];
            }
#pragma unroll
            for (int mi = 0; mi < 2; mi++)
#pragma unroll
                for (int j = 0; j < 4; j++) mma16(acc[mi][j], af[mi], bf[j]);
        }
    }

    // ctx partial (fp32; combined later)
#pragma unroll
    for (int mi = 0; mi < 2; mi++) {
        int r0 = row0 + wm + mi * 16 + g;
#pragma unroll
        for (int j = 0; j < 4; j++) {
            int col = wn + j * 8 + tg * 2;
            *(float2*)(ctxp + base + (size_t)r0 * DD + col) =
                make_float2(acc[mi][j][0], acc[mi][j][1]);
            *(float2*)(ctxp + base + (size_t)(r0 + 8) * DD + col) =
                make_float2(acc[mi][j][2], acc[mi][j][3]);
        }
    }
}

// ---------------- combine ctx partials -> fp16 ---------------------------------
__global__ void ctx_combine(const float4* __restrict__ a, const float4* __restrict__ b,
                            __half2* __restrict__ o, int n4)
{
    int i = blockIdx.x * blockDim.x + threadIdx.x;
    if (i < n4) {
        float4 x = a[i], y = b[i];
        o[2*i]   = __floats2half2_rn(x.x + y.x, x.y + y.y);
        o[2*i+1] = __floats2half2_rn(x.z + y.z, x.w + y.w);
    }
}

// ---------------- residual + two-partial sum + bias + layernorm ----------------
__global__ void add_ln2_kernel(const float* __restrict__ x,
                               const float* __restrict__ y1,
                               const float* __restrict__ y2,
                               const float* __restrict__ bias,
                               const float* __restrict__ g, const float* __restrict__ be,
                               float* __restrict__ po, __half* __restrict__ poh)
{
    size_t row = blockIdx.x;
    const float* px  = x  + row * DD;
    const float* py1 = y1 + row * DD;
    const float* py2 = y2 + row * DD;
    int t = threadIdx.x;
    __shared__ float red[256];

    float a0 = px[t]       + py1[t]       + py2[t]       + bias[t];
    float a1 = px[t + 256] + py1[t + 256] + py2[t + 256] + bias[t + 256];
    float a2 = px[t + 512] + py1[t + 512] + py2[t + 512] + bias[t + 512];

    red[t] = a0 + a1 + a2; __syncthreads();
    for (int s = 128; s > 0; s >>= 1) { if (t < s) red[t] += red[t + s]; __syncthreads(); }
    float mean = red[0] * (1.0f / DD); __syncthreads();

    float d0 = a0 - mean, d1 = a1 - mean, d2 = a2 - mean;
    red[t] = d0 * d0 + d1 * d1 + d2 * d2; __syncthreads();
    for (int s = 128; s > 0; s >>= 1) { if (t < s) red[t] += red[t + s]; __syncthreads(); }
    float rstd = rsqrtf(red[0] * (1.0f / DD) + 1e-5f);

    float o0 = d0 * rstd * g[t]       + be[t];
    float o1 = d1 * rstd * g[t + 256] + be[t + 256];
    float o2 = d2 * rstd * g[t + 512] + be[t + 512];
    po[row * DD + t] = o0; po[row * DD + t + 256] = o1; po[row * DD + t + 512] = o2;
    if (poh) {
        poh[row * DD + t]       = __float2half_rn(o0);
        poh[row * DD + t + 256] = __float2half_rn(o1);
        poh[row * DD + t + 512] = __float2half_rn(o2);
    }
}

// ---------------- launcher ----------------------------------------------------
extern "C" void kernel_launch(void* const* d_in, const int* in_sizes, int n_in,
                              void* d_out, int out_size)
{
    const float* x   = (const float*)d_in[0];
    const float* Wq  = (const float*)d_in[1];
    const float* bq  = (const float*)d_in[2];
    const float* Wk  = (const float*)d_in[3];
    const float* bk  = (const float*)d_in[4];
    const float* Wv  = (const float*)d_in[5];
    const float* bv  = (const float*)d_in[6];
    const float* Wo  = (const float*)d_in[7];
    const float* bo  = (const float*)d_in[8];
    const float* W1  = (const float*)d_in[9];
    const float* b1  = (const float*)d_in[10];
    const float* W2  = (const float*)d_in[11];
    const float* b2  = (const float*)d_in[12];
    const float* g1  = (const float*)d_in[13];
    const float* be1 = (const float*)d_in[14];
    const float* g2  = (const float*)d_in[15];
    const float* be2 = (const float*)d_in[16];

    float* out  = (float*)d_out;                 // x2: [2,2048,768]
    float* attn = out + X2_ELEMS;                // attn_weights: [2,12,2048,2048]

    __half *Qh, *Kh, *Vh, *Vth, *ctxh, *x1h, *ffh, *xh;
    __half *Wqh, *Wkh, *Wvh, *Woh, *W1h, *W2h;
    float *X1p, *T2p, *T2bp, *psp, *rip;
    cudaGetSymbolAddress((void**)&Qh,   g_Qh);
    cudaGetSymbolAddress((void**)&Kh,   g_Kh);
    cudaGetSymbolAddress((void**)&Vh,   g_Vh);
    cudaGetSymbolAddress((void**)&Vth,  g_Vth);
    cudaGetSymbolAddress((void**)&ctxh, g_ctxh);
    cudaGetSymbolAddress((void**)&x1h,  g_x1h);
    cudaGetSymbolAddress((void**)&ffh,  g_ffh);
    cudaGetSymbolAddress((void**)&xh,   g_xh);
    cudaGetSymbolAddress((void**)&Wqh,  g_Wqh);
    cudaGetSymbolAddress((void**)&Wkh,  g_Wkh);
    cudaGetSymbolAddress((void**)&Wvh,  g_Wvh);
    cudaGetSymbolAddress((void**)&Woh,  g_Woh);
    cudaGetSymbolAddress((void**)&W1h,  g_W1h);
    cudaGetSymbolAddress((void**)&W2h,  g_W2h);
    cudaGetSymbolAddress((void**)&X1p,  g_x1);
    cudaGetSymbolAddress((void**)&T2p,  g_t2);
    cudaGetSymbolAddress((void**)&T2bp, g_t2b);
    cudaGetSymbolAddress((void**)&psp,  g_ps);
    cudaGetSymbolAddress((void**)&rip,  g_ri);

    static int attr_set = 0;
    if (!attr_set) {
        cudaFuncSetAttribute(attn_pv_h, cudaFuncAttributeMaxDynamicSharedMemorySize,
                             APV_SMEM);
        cudaFuncSetAttribute(dense_h, cudaFuncAttributeMaxDynamicSharedMemorySize,
                             DENSE_SMEM);
        attr_set = 1;
    }

    // merged prep: x -> fp16 + all weight transposes (one launch)
    prep_all<<<PREP_XBLK + 6912, 256>>>(
        (const float4*)x, (__half2*)xh,
        Wq, Wqh, Wk, Wkh, Wv, Wvh, Wo, Woh, W1, W1h, W2, W2h);

    // merged Q/K/V projections (fp16 out)
    dense_h<<<dim3(DD/128, MM/128, 3), 256, DENSE_SMEM>>>(
        xh, Wqh, bq, Qh, nullptr, Wkh, bk, Kh, nullptr, Wvh, bv, Vh, nullptr,
        DD, DD, 0, 0);

    // per-head V transpose [seq][dk] -> [dk][seq]
    v_transpose<<<dim3(SS/64, BB*HH), dim3(64, 4)>>>(Vh, Vth);

    // softmax exp-sum partials (no max shift; scores O(1))
    stats_h<<<dim3(SS/128, SS/128, BB*HH), 256>>>(Qh, Kh, psp);
    rowstats<<<(BB*HH*SS + 255) / 256, 256>>>(psp, rip);

    // col-split attention: write attn once, ctx partials (fp32)
    attn_pv_h<<<dim3(SS/128, 2, BB*HH), 256, APV_SMEM>>>(
        Qh, Kh, Vth, rip, attn, T2p, T2bp);

    // combine ctx partials -> fp16
    ctx_combine<<<(MM*DD/4 + 255) / 256, 256>>>(
        (const float4*)T2p, (const float4*)T2bp, (__half2*)ctxh, MM*DD/4);

    // attn_out = ctx @ Wo (split-K=2 partials, bias deferred to LN)
    dense_h<<<dim3(DD/128, MM/128, 2), 256, DENSE_SMEM>>>(
        ctxh, Woh, nullptr, nullptr, T2p, Woh, nullptr, nullptr, T2bp,
        nullptr, nullptr, nullptr, nullptr, DD, DD, 0, 1);

    // x1 = LN(x + p1 + p2 + bo) -> fp32 + fp16
    add_ln2_kernel<<<MM, 256>>>(x, T2p, T2bp, bo, g1, be1, X1p, x1h);

    // ff = relu(x1 @ W1 + b1) fp16
    dense_h<<<dim3(DFF/128, MM/128, 1), 256, DENSE_SMEM>>>(
        x1h, W1h, b1, ffh, nullptr, nullptr, nullptr, nullptr, nullptr,
        nullptr, nullptr, nullptr, nullptr, DD, DFF, 1, 0);

    // ff2 = ff @ W2 (split-K=2 partials, bias deferred to LN)
    dense_h<<<dim3(DD/128, MM/128, 2), 256, DENSE_SMEM>>>(
        ffh, W2h, nullptr, nullptr, T2p, W2h, nullptr, nullptr, T2bp,
        nullptr, nullptr, nullptr, nullptr, DFF, DD, 0, 1);

    // x2 = LN(x1 + p1 + p2 + b2) -> output
    add_ln2_kernel<<<MM, 256>>>(X1p, T2p, T2bp, b2, g2, be2, out, nullptr);
}

// round 17
// speedup vs baseline: 1.0150x; 1.0108x over previous
#include <cuda_runtime.h>
#include <cuda_fp16.h>
#include <cstdint>
#include <cstddef>

#define BB 2
#define SS 2048
#define DD 768
#define HH 12
#define DK 64
#define DFF 3072
#define MM (BB*SS)                 // 4096
#define X2_ELEMS ((size_t)MM*DD)   // 3145728
#define NBLK 16                    // SS/128 col blocks per row
#define EXC 0.18033688011112042f   // 0.125 * log2(e)

// ---------------- scratch (static device globals; no allocation) -------------
__device__ __half g_Qh[(size_t)MM*DD];
__device__ __half g_Kh[(size_t)MM*DD];
__device__ __half g_Vh[(size_t)MM*DD];
__device__ __half g_Vth[(size_t)BB*HH*DK*SS];   // per-head V transposed [dk][seq]
__device__ __half g_ctxh[(size_t)MM*DD];
__device__ float  g_x1[(size_t)MM*DD];
__device__ __half g_x1h[(size_t)MM*DD];
__device__ float  g_t2[(size_t)MM*DD];
__device__ float  g_t2b[(size_t)MM*DD];
__device__ __half g_ffh[(size_t)MM*DFF];
__device__ __half g_xh[(size_t)MM*DD];
// transposed fp16 weights [N][K]
__device__ __half g_Wqh[(size_t)DD*DD];
__device__ __half g_Wkh[(size_t)DD*DD];
__device__ __half g_Wvh[(size_t)DD*DD];
__device__ __half g_Woh[(size_t)DD*DD];
__device__ __half g_W1h[(size_t)DFF*DD];
__device__ __half g_W2h[(size_t)DD*DFF];
// softmax partial sums / row inv-sums
__device__ float g_ps[(size_t)BB*HH*NBLK*SS];
__device__ float g_ri[(size_t)BB*HH*SS];

// ---------------- helpers ----------------------------------------------------
__device__ __forceinline__ void mma16(float* c, const uint32_t* a, const uint32_t* b) {
    asm volatile(
        "mma.sync.aligned.m16n8k16.row.col.f32.f16.f16.f32 "
        "{%0,%1,%2,%3},{%4,%5,%6,%7},{%8,%9},{%0,%1,%2,%3};\n"
        : "+f"(c[0]), "+f"(c[1]), "+f"(c[2]), "+f"(c[3])
        : "r"(a[0]), "r"(a[1]), "r"(a[2]), "r"(a[3]), "r"(b[0]), "r"(b[1]));
}
__device__ __forceinline__ float ex2(float x) {
    float r;
    asm("ex2.approx.f32 %0, %1;" : "=f"(r) : "f"(x));
    return r;
}
__device__ __forceinline__ void cp16(uint32_t smem_addr, const void* gptr) {
    asm volatile("cp.async.cg.shared.global [%0], [%1], 16;\n"
                 :: "r"(smem_addr), "l"(gptr));
}
__device__ __forceinline__ void cp_commit() {
    asm volatile("cp.async.commit_group;\n" ::: "memory");
}
template<int N>
__device__ __forceinline__ void cp_wait() {
    asm volatile("cp.async.wait_group %0;\n" :: "n"(N) : "memory");
}
__device__ __forceinline__ uint32_t smem_u32(const void* p) {
    uint32_t a;
    asm("{ .reg .u64 t; cvta.to.shared.u64 t, %1; cvt.u32.u64 %0, t; }" : "=r"(a) : "l"(p));
    return a;
}
__device__ __forceinline__ uint32_t h2u(__half2 h) {
    return *reinterpret_cast<uint32_t*>(&h);
}
__device__ __forceinline__ int kperm(int l) {
    int r = l & 7;
    int p = (r < 4) ? (2 * r) : (2 * (r - 4) + 1);
    return (l & ~7) | p;
}

// ---------------- merged prep: x->fp16 + 6 weight transposes -------------------
#define PREP_XBLK 3072
__global__ void prep_all(
    const float4* __restrict__ x,  __half2* __restrict__ xh,
    const float* __restrict__ wq, __half* __restrict__ wqh,
    const float* __restrict__ wk, __half* __restrict__ wkh,
    const float* __restrict__ wv, __half* __restrict__ wvh,
    const float* __restrict__ wo, __half* __restrict__ woh,
    const float* __restrict__ w1, __half* __restrict__ w1h,
    const float* __restrict__ w2, __half* __restrict__ w2h)
{
    int bid = blockIdx.x;
    int tid = threadIdx.x;
    if (bid < PREP_XBLK) {
        int i = bid * 256 + tid;
        float4 v = x[i];
        xh[i * 2]     = __floats2half2_rn(v.x, v.y);
        xh[i * 2 + 1] = __floats2half2_rn(v.z, v.w);
        return;
    }
    int t = bid - PREP_XBLK;
    const float* in; __half* out; int R, C;
    if      (t < 576)  { in = wq; out = wqh; R = DD;  C = DD;  }
    else if (t < 1152) { in = wk; out = wkh; R = DD;  C = DD;  t -= 576; }
    else if (t < 1728) { in = wv; out = wvh; R = DD;  C = DD;  t -= 1152; }
    else if (t < 2304) { in = wo; out = woh; R = DD;  C = DD;  t -= 1728; }
    else if (t < 4608) { in = w1; out = w1h; R = DD;  C = DFF; t -= 2304; }
    else               { in = w2; out = w2h; R = DFF; C = DD;  t -= 4608; }
    int nx = C / 32;
    int c0 = (t % nx) * 32, r0 = (t / nx) * 32;
    __shared__ float tt[32][33];
    int xx = tid & 31, yy = tid >> 5;    // 32 x 8
#pragma unroll
    for (int i = 0; i < 32; i += 8)
        tt[yy + i][xx] = in[(size_t)(r0 + yy + i) * C + c0 + xx];
    __syncthreads();
#pragma unroll
    for (int i = 0; i < 32; i += 8)
        out[(size_t)(c0 + yy + i) * R + r0 + xx] = __float2half_rn(tt[xx][yy + i]);
}

// ---------------- prep: per-head V [seq][dk] -> [dk][seq] fp16 -----------------
__global__ void v_transpose(const __half* __restrict__ Vh, __half* __restrict__ Vt)
{
    __shared__ __half t[64][72];
    int z = blockIdx.y;
    int b = z / HH, h = z % HH;
    int s0 = blockIdx.x * 64;
    const __half* src = Vh + (size_t)b * SS * DD + (size_t)h * DK;
    __half* dst = Vt + (size_t)z * DK * SS;
    int x = threadIdx.x, y = threadIdx.y;    // 64 x 4
#pragma unroll
    for (int i = 0; i < 64; i += 4)
        t[y + i][x] = src[(size_t)(s0 + y + i) * DD + x];
    __syncthreads();
#pragma unroll
    for (int i = 0; i < 64; i += 4)
        dst[(size_t)(y + i) * SS + s0 + x] = t[x][y + i];
}

// ---------------- fp16 dense GEMM:  C = A[M,K] @ Bt[N,K]^T (+ bias) -----------
// 128x128 tile, BK=64, 8 warps (warp 64x32), m16n8k16, k-permuted LDS.64.
// splitk: gridDim.z=2 computes K-halves; z selects output triple (partials).
#define DSTR 40   // u32 per 64-half row; half-warp banks 8g+2tg distinct
#define DENSE_SMEM (2 * 2 * 128 * DSTR * 4)   // 81920 B (A+B, 2 stages)
__global__ void __launch_bounds__(256, 2) dense_h(
    const __half* __restrict__ A,
    const __half* __restrict__ Bt0, const float* __restrict__ bias0,
    __half* __restrict__ H0, float* __restrict__ F0,
    const __half* __restrict__ Bt1, const float* __restrict__ bias1,
    __half* __restrict__ H1, float* __restrict__ F1,
    const __half* __restrict__ Bt2, const float* __restrict__ bias2,
    __half* __restrict__ H2, float* __restrict__ F2,
    int K, int Ntot, int relu, int splitk)
{
    extern __shared__ uint32_t dsm[];
    uint32_t* As = dsm;                    // 2 x 128 x DSTR
    uint32_t* Bs = dsm + 2 * 128 * DSTR;   // 2 x 128 x DSTR

    const int tid  = threadIdx.x;
    const int wid  = tid >> 5;
    const int lane = tid & 31;
    const int g    = lane >> 2;
    const int tg   = lane & 3;
    const int wm   = (wid >> 2) * 64;
    const int wn   = (wid & 3) * 32;

    const __half* Bt = Bt0; const float* bias = bias0;
    __half* H = H0; float* F = F0;
    if (blockIdx.z == 1) { Bt = Bt1; bias = bias1; H = H1; F = F1; }
    else if (blockIdx.z == 2) { Bt = Bt2; bias = bias2; H = H2; F = F2; }

    int keff = K, koff = 0;
    if (splitk) { keff = K >> 1; if (blockIdx.z == 1) koff = keff; }

    const int m0 = blockIdx.y * 128;
    const int n0 = blockIdx.x * 128;
    const __half* Ab = A + (size_t)m0 * K + koff;
    const __half* Bb = Bt + (size_t)n0 * K + koff;

    const uint32_t sA = smem_u32(As);
    const uint32_t sB = smem_u32(Bs);

    auto issue = [&](int ch, int st) {
        int k0 = ch * 64;
        uint32_t abuf = sA + st * (128 * DSTR) * 4;
        uint32_t bbuf = sB + st * (128 * DSTR) * 4;
#pragma unroll
        for (int i = 0; i < 4; i++) {
            int idx = tid + i * 256;
            int r = idx >> 3, c = idx & 7;
            cp16(abuf + (r * DSTR + c * 4) * 4, Ab + (size_t)r * K + k0 + c * 8);
            cp16(bbuf + (r * DSTR + c * 4) * 4, Bb + (size_t)r * K + k0 + c * 8);
        }
        cp_commit();
    };

    float c[4][4][4];
#pragma unroll
    for (int mi = 0; mi < 4; mi++)
#pragma unroll
        for (int j = 0; j < 4; j++)
#pragma unroll
            for (int r = 0; r < 4; r++) c[mi][j][r] = 0.f;

    const int nc = keff / 64;
    issue(0, 0);

    for (int kc = 0; kc < nc; kc++) {
        const int st = kc & 1;
        if (kc + 1 < nc) { issue(kc + 1, st ^ 1); cp_wait<1>(); }
        else             { cp_wait<0>(); }
        __syncthreads();

        const uint32_t* Ac = As + st * (128 * DSTR);
        const uint32_t* Bc = Bs + st * (128 * DSTR);
#pragma unroll
        for (int step = 0; step < 4; step++) {
            const int ko = step * 8;
            uint32_t af[4][4], bf[4][2];
#pragma unroll
            for (int mi = 0; mi < 4; mi++) {
                int m = wm + mi * 16 + g;
                uint2 p0 = *(const uint2*)&Ac[m * DSTR + ko + 2 * tg];
                uint2 p1 = *(const uint2*)&Ac[(m + 8) * DSTR + ko + 2 * tg];
                af[mi][0] = p0.x; af[mi][2] = p0.y;
                af[mi][1] = p1.x; af[mi][3] = p1.y;
            }
#pragma unroll
            for (int j = 0; j < 4; j++) {
                int n = wn + j * 8 + g;
                uint2 q = *(const uint2*)&Bc[n * DSTR + ko + 2 * tg];
                bf[j][0] = q.x; bf[j][1] = q.y;
            }
#pragma unroll
            for (int mi = 0; mi < 4; mi++)
#pragma unroll
                for (int j = 0; j < 4; j++) mma16(c[mi][j], af[mi], bf[j]);
        }
        __syncthreads();
    }

    // epilogue
#pragma unroll
    for (int mi = 0; mi < 4; mi++) {
        int r0 = m0 + wm + mi * 16 + g;
#pragma unroll
        for (int j = 0; j < 4; j++) {
            int col = n0 + wn + j * 8 + tg * 2;
            float2 bb = bias ? *(const float2*)(bias + col) : make_float2(0.f, 0.f);
            float v0 = c[mi][j][0] + bb.x;
            float v1 = c[mi][j][1] + bb.y;
            float v2 = c[mi][j][2] + bb.x;
            float v3 = c[mi][j][3] + bb.y;
            if (relu) {
                v0 = fmaxf(v0, 0.f); v1 = fmaxf(v1, 0.f);
                v2 = fmaxf(v2, 0.f); v3 = fmaxf(v3, 0.f);
            }
            if (H) {
                *(uint32_t*)(H + (size_t)r0 * Ntot + col)       = h2u(__floats2half2_rn(v0, v1));
                *(uint32_t*)(H + (size_t)(r0 + 8) * Ntot + col) = h2u(__floats2half2_rn(v2, v3));
            }
            if (F) {
                *(float2*)(F + (size_t)r0 * Ntot + col)       = make_float2(v0, v1);
                *(float2*)(F + (size_t)(r0 + 8) * Ntot + col) = make_float2(v2, v3);
            }
        }
    }
}

// ---------------- stats: Q@K^T (fp16) -> per-block exp-sum partials ------------
#define HSTR 40   // u32 units per 64-half row; banks 8g+2tg conflict-free
__global__ void __launch_bounds__(256, 2) stats_h(
    const __half* __restrict__ Q, const __half* __restrict__ Km,
    float* __restrict__ ps)
{
    __shared__ uint32_t Qs[128 * HSTR];
    __shared__ uint32_t Ks[128 * HSTR];
    __shared__ float sm_s[128][4];

    const int tid  = threadIdx.x;
    const int wid  = tid >> 5;
    const int lane = tid & 31;
    const int g    = lane >> 2;
    const int tg   = lane & 3;
    const int wm   = (wid >> 2) * 64;
    const int wn   = (wid & 3) * 32;

    const int z = blockIdx.z;
    const int b = z / HH, h = z % HH;
    const size_t base = (size_t)b * SS * DD + (size_t)h * DK;
    const int row0 = blockIdx.y * 128;
    const int col0 = blockIdx.x * 128;

    const uint32_t sQ = smem_u32(Qs);
    const uint32_t sK = smem_u32(Ks);

#pragma unroll
    for (int i = 0; i < 4; i++) {
        int idx = tid + i * 256;
        int r = idx >> 3, cch = idx & 7;
        cp16(sQ + (r * HSTR + cch * 4) * 4, Q  + base + (size_t)(row0 + r) * DD + cch * 8);
        cp16(sK + (r * HSTR + cch * 4) * 4, Km + base + (size_t)(col0 + r) * DD + cch * 8);
    }
    cp_commit();
    cp_wait<0>();
    __syncthreads();

    float c[4][4][4];
#pragma unroll
    for (int mi = 0; mi < 4; mi++)
#pragma unroll
        for (int j = 0; j < 4; j++)
#pragma unroll
            for (int r = 0; r < 4; r++) c[mi][j][r] = 0.f;

#pragma unroll
    for (int step = 0; step < 4; step++) {
        const int ko = step * 8;
        uint32_t af[4][4], bf[4][2];
#pragma unroll
        for (int mi = 0; mi < 4; mi++) {
            int m = wm + mi * 16 + g;
            uint2 p0 = *(const uint2*)&Qs[m * HSTR + ko + 2 * tg];
            uint2 p1 = *(const uint2*)&Qs[(m + 8) * HSTR + ko + 2 * tg];
            af[mi][0] = p0.x; af[mi][2] = p0.y;
            af[mi][1] = p1.x; af[mi][3] = p1.y;
        }
#pragma unroll
        for (int j = 0; j < 4; j++) {
            int n = wn + j * 8 + g;
            uint2 q = *(const uint2*)&Ks[n * HSTR + ko + 2 * tg];
            bf[j][0] = q.x; bf[j][1] = q.y;
        }
#pragma unroll
        for (int mi = 0; mi < 4; mi++)
#pragma unroll
            for (int j = 0; j < 4; j++) mma16(c[mi][j], af[mi], bf[j]);
    }

#pragma unroll
    for (int mi = 0; mi < 4; mi++) {
#pragma unroll
        for (int half = 0; half < 2; half++) {
            float s = 0.f;
#pragma unroll
            for (int j = 0; j < 4; j++)
                s += ex2(c[mi][j][half*2] * EXC) + ex2(c[mi][j][half*2+1] * EXC);
            s += __shfl_xor_sync(0xffffffffu, s, 1);
            s += __shfl_xor_sync(0xffffffffu, s, 2);
            if (tg == 0) {
                int row = wm + mi * 16 + g + half * 8;
                sm_s[row][wid & 3] = s;
            }
        }
    }
    __syncthreads();

    if (tid < 128) {
        float s = sm_s[tid][0] + sm_s[tid][1] + sm_s[tid][2] + sm_s[tid][3];
        ps[((size_t)z * NBLK + blockIdx.x) * SS + row0 + tid] = s;
    }
}

// ---------------- combine partial sums -> per-row 1/sum ------------------------
__global__ void rowstats(const float* __restrict__ ps, float* __restrict__ ri)
{
    int idx = blockIdx.x * blockDim.x + threadIdx.x;
    if (idx >= BB * HH * SS) return;
    int z = idx / SS, row = idx % SS;
    float s = 0.f;
#pragma unroll
    for (int blk = 0; blk < NBLK; blk++)
        s += ps[((size_t)z * NBLK + blk) * SS + row];
    ri[idx] = 1.0f / s;
}

// ---------------- attn_pv: recompute S (fp16), write attn fp32, ctx = P@V -----
#define APV_SMEM ((128*HSTR * 4) * 4 + 1024)
__global__ void __launch_bounds__(256) attn_pv_h(
    const __half* __restrict__ Q, const __half* __restrict__ Km,
    const __half* __restrict__ Vt,
    const float* __restrict__ ri,
    float* __restrict__ attn, __half* __restrict__ ctx)
{
    extern __shared__ uint32_t smu[];
    uint32_t* Qs = smu;                       // 128 x HSTR
    uint32_t* Ps = Qs + 128 * HSTR;           // 128 x HSTR (k-permuted layout)
    uint32_t* Ks = Ps + 128 * HSTR;           // 2 x 64 x HSTR
    uint32_t* Vs = Ks + 2 * 64 * HSTR;        // 2 x 64 x HSTR
    float* s_i = (float*)(Vs + 2 * 64 * HSTR);

    const int tid  = threadIdx.x;
    const int wid  = tid >> 5;
    const int lane = tid & 31;
    const int g    = lane >> 2;
    const int tg   = lane & 3;
    const int wm   = (wid >> 1) * 32;   // 4 row groups of 32
    const int wn   = (wid & 1) * 32;    // 2 col groups of 32

    const int z = blockIdx.y;
    const int b = z / HH, h = z % HH;
    const size_t base = (size_t)b * SS * DD + (size_t)h * DK;
    const int row0 = blockIdx.x * 128;
    float* Ab = attn + (size_t)z * SS * SS + (size_t)row0 * SS;
    const __half* Vz = Vt + (size_t)z * DK * SS;

    const uint32_t sQ = smem_u32(Qs);
    const uint32_t sK = smem_u32(Ks);
    const uint32_t sV = smem_u32(Vs);

    if (tid < 128)
        s_i[tid] = ri[(size_t)z * SS + row0 + tid];

    auto issueKV = [&](int cc, int st) {
#pragma unroll
        for (int i = 0; i < 2; i++) {
            int idx = tid + i * 256;
            int r = idx >> 3, cch = idx & 7;
            cp16(sK + ((st * 64 + r) * HSTR + cch * 4) * 4,
                 Km + base + (size_t)(cc * 64 + r) * DD + cch * 8);
            cp16(sV + ((st * 64 + r) * HSTR + cch * 4) * 4,
                 Vz + (size_t)r * SS + cc * 64 + cch * 8);
        }
        cp_commit();
    };

#pragma unroll
    for (int i = 0; i < 4; i++) {
        int idx = tid + i * 256;
        int r = idx >> 3, cch = idx & 7;
        cp16(sQ + (r * HSTR + cch * 4) * 4, Q + base + (size_t)(row0 + r) * DD + cch * 8);
    }
    issueKV(0, 0);

    float acc[2][4][4];
#pragma unroll
    for (int mi = 0; mi < 2; mi++)
#pragma unroll
        for (int j = 0; j < 4; j++)
#pragma unroll
            for (int r = 0; r < 4; r++) acc[mi][j][r] = 0.f;

    for (int cc = 0; cc < SS / 64; cc++) {
        const int st = cc & 1;
        if (cc + 1 < SS / 64) { issueKV(cc + 1, st ^ 1); cp_wait<1>(); }
        else                  { cp_wait<0>(); }
        __syncthreads();   // KV[st] ready; Ps from prev iter consumed

        const uint32_t* Kc = Ks + st * 64 * HSTR;
        const uint32_t* Vc = Vs + st * 64 * HSTR;

        // ---- S = Q @ Kc^T (k = dk = 64); fetch chain matches stats_h ----
        float c[2][4][4];
#pragma unroll
        for (int mi = 0; mi < 2; mi++)
#pragma unroll
            for (int j = 0; j < 4; j++)
#pragma unroll
                for (int r = 0; r < 4; r++) c[mi][j][r] = 0.f;

#pragma unroll
        for (int step = 0; step < 4; step++) {
            const int ko = step * 8;
            uint32_t af[2][4], bf[4][2];
#pragma unroll
            for (int mi = 0; mi < 2; mi++) {
                int m = wm + mi * 16 + g;
                uint2 p0 = *(const uint2*)&Qs[m * HSTR + ko + 2 * tg];
                uint2 p1 = *(const uint2*)&Qs[(m + 8) * HSTR + ko + 2 * tg];
                af[mi][0] = p0.x; af[mi][2] = p0.y;
                af[mi][1] = p1.x; af[mi][3] = p1.y;
            }
#pragma unroll
            for (int j = 0; j < 4; j++) {
                int n = wn + j * 8 + g;
                uint2 q = *(const uint2*)&Kc[n * HSTR + ko + 2 * tg];
                bf[j][0] = q.x; bf[j][1] = q.y;
            }
#pragma unroll
            for (int mi = 0; mi < 2; mi++)
#pragma unroll
                for (int j = 0; j < 4; j++) mma16(c[mi][j], af[mi], bf[j]);
        }

        // ---- normalize (no shift, ex2): write attn fp32, stage P (k-permuted) ----
#pragma unroll
        for (int mi = 0; mi < 2; mi++) {
#pragma unroll
            for (int half = 0; half < 2; half++) {
                int row = wm + mi * 16 + g + half * 8;
                float inv = s_i[row];
#pragma unroll
                for (int j = 0; j < 4; j++) {
                    float p0 = ex2(c[mi][j][half*2]   * EXC) * inv;
                    float p1 = ex2(c[mi][j][half*2+1] * EXC) * inv;
                    int col = wn + j * 8 + 2 * tg;
                    *(float2*)(Ab + (size_t)row * SS + cc * 64 + col) = make_float2(p0, p1);
                    Ps[row * HSTR + kperm(wn / 2 + 4 * j + tg)] = h2u(__floats2half2_rn(p0, p1));
                }
            }
        }
        __syncthreads();   // Ps complete

        // ---- ctx += P @ Vc^T: af permuted LDS.64 (pre-permuted Ps), bf straight ----
#pragma unroll
        for (int step = 0; step < 4; step++) {
            const int ko = step * 8;
            uint32_t af[2][4], bf[4][2];
#pragma unroll
            for (int mi = 0; mi < 2; mi++) {
                int m = wm + mi * 16 + g;
                uint2 p0 = *(const uint2*)&Ps[m * HSTR + ko + 2 * tg];
                uint2 p1 = *(const uint2*)&Ps[(m + 8) * HSTR + ko + 2 * tg];
                af[mi][0] = p0.x; af[mi][2] = p0.y;
                af[mi][1] = p1.x; af[mi][3] = p1.y;
            }
#pragma unroll
            for (int j = 0; j < 4; j++) {
                int n = wn + j * 8 + g;
                bf[j][0] = Vc[n * HSTR + ko + tg];
                bf[j][1] = Vc[n * HSTR + ko + tg + 4];
            }
#pragma unroll
            for (int mi = 0; mi < 2; mi++)
#pragma unroll
                for (int j = 0; j < 4; j++) mma16(acc[mi][j], af[mi], bf[j]);
        }
    }

    // ctx fp16 (feeds Wo GEMM)
#pragma unroll
    for (int mi = 0; mi < 2; mi++) {
        int r0 = row0 + wm + mi * 16 + g;
#pragma unroll
        for (int j = 0; j < 4; j++) {
            int col = wn + j * 8 + tg * 2;
            *(uint32_t*)(ctx + base + (size_t)r0 * DD + col) =
                h2u(__floats2half2_rn(acc[mi][j][0], acc[mi][j][1]));
            *(uint32_t*)(ctx + base + (size_t)(r0 + 8) * DD + col) =
                h2u(__floats2half2_rn(acc[mi][j][2], acc[mi][j][3]));
        }
    }
}

// ---------------- residual + two-partial sum + bias + layernorm ----------------
__global__ void add_ln2_kernel(const float* __restrict__ x,
                               const float* __restrict__ y1,
                               const float* __restrict__ y2,
                               const float* __restrict__ bias,
                               const float* __restrict__ g, const float* __restrict__ be,
                               float* __restrict__ po, __half* __restrict__ poh)
{
    size_t row = blockIdx.x;
    const float* px  = x  + row * DD;
    const float* py1 = y1 + row * DD;
    const float* py2 = y2 + row * DD;
    int t = threadIdx.x;
    __shared__ float red[256];

    float a0 = px[t]       + py1[t]       + py2[t]       + bias[t];
    float a1 = px[t + 256] + py1[t + 256] + py2[t + 256] + bias[t + 256];
    float a2 = px[t + 512] + py1[t + 512] + py2[t + 512] + bias[t + 512];

    red[t] = a0 + a1 + a2; __syncthreads();
    for (int s = 128; s > 0; s >>= 1) { if (t < s) red[t] += red[t + s]; __syncthreads(); }
    float mean = red[0] * (1.0f / DD); __syncthreads();

    float d0 = a0 - mean, d1 = a1 - mean, d2 = a2 - mean;
    red[t] = d0 * d0 + d1 * d1 + d2 * d2; __syncthreads();
    for (int s = 128; s > 0; s >>= 1) { if (t < s) red[t] += red[t + s]; __syncthreads(); }
    float rstd = rsqrtf(red[0] * (1.0f / DD) + 1e-5f);

    float o0 = d0 * rstd * g[t]       + be[t];
    float o1 = d1 * rstd * g[t + 256] + be[t + 256];
    float o2 = d2 * rstd * g[t + 512] + be[t + 512];
    po[row * DD + t] = o0; po[row * DD + t + 256] = o1; po[row * DD + t + 512] = o2;
    if (poh) {
        poh[row * DD + t]       = __float2half_rn(o0);
        poh[row * DD + t + 256] = __float2half_rn(o1);
        poh[row * DD + t + 512] = __float2half_rn(o2);
    }
}

// ---------------- launcher ----------------------------------------------------
extern "C" void kernel_launch(void* const* d_in, const int* in_sizes, int n_in,
                              void* d_out, int out_size)
{
    const float* x   = (const float*)d_in[0];
    const float* Wq  = (const float*)d_in[1];
    const float* bq  = (const float*)d_in[2];
    const float* Wk  = (const float*)d_in[3];
    const float* bk  = (const float*)d_in[4];
    const float* Wv  = (const float*)d_in[5];
    const float* bv  = (const float*)d_in[6];
    const float* Wo  = (const float*)d_in[7];
    const float* bo  = (const float*)d_in[8];
    const float* W1  = (const float*)d_in[9];
    const float* b1  = (const float*)d_in[10];
    const float* W2  = (const float*)d_in[11];
    const float* b2  = (const float*)d_in[12];
    const float* g1  = (const float*)d_in[13];
    const float* be1 = (const float*)d_in[14];
    const float* g2  = (const float*)d_in[15];
    const float* be2 = (const float*)d_in[16];

    float* out  = (float*)d_out;                 // x2: [2,2048,768]
    float* attn = out + X2_ELEMS;                // attn_weights: [2,12,2048,2048]

    __half *Qh, *Kh, *Vh, *Vth, *ctxh, *x1h, *ffh, *xh;
    __half *Wqh, *Wkh, *Wvh, *Woh, *W1h, *W2h;
    float *X1p, *T2p, *T2bp, *psp, *rip;
    cudaGetSymbolAddress((void**)&Qh,   g_Qh);
    cudaGetSymbolAddress((void**)&Kh,   g_Kh);
    cudaGetSymbolAddress((void**)&Vh,   g_Vh);
    cudaGetSymbolAddress((void**)&Vth,  g_Vth);
    cudaGetSymbolAddress((void**)&ctxh, g_ctxh);
    cudaGetSymbolAddress((void**)&x1h,  g_x1h);
    cudaGetSymbolAddress((void**)&ffh,  g_ffh);
    cudaGetSymbolAddress((void**)&xh,   g_xh);
    cudaGetSymbolAddress((void**)&Wqh,  g_Wqh);
    cudaGetSymbolAddress((void**)&Wkh,  g_Wkh);
    cudaGetSymbolAddress((void**)&Wvh,  g_Wvh);
    cudaGetSymbolAddress((void**)&Woh,  g_Woh);
    cudaGetSymbolAddress((void**)&W1h,  g_W1h);
    cudaGetSymbolAddress((void**)&W2h,  g_W2h);
    cudaGetSymbolAddress((void**)&X1p,  g_x1);
    cudaGetSymbolAddress((void**)&T2p,  g_t2);
    cudaGetSymbolAddress((void**)&T2bp, g_t2b);
    cudaGetSymbolAddress((void**)&psp,  g_ps);
    cudaGetSymbolAddress((void**)&rip,  g_ri);

    static int attr_set = 0;
    if (!attr_set) {
        cudaFuncSetAttribute(attn_pv_h, cudaFuncAttributeMaxDynamicSharedMemorySize,
                             APV_SMEM);
        cudaFuncSetAttribute(dense_h, cudaFuncAttributeMaxDynamicSharedMemorySize,
                             DENSE_SMEM);
        attr_set = 1;
    }

    // merged prep: x -> fp16 + all weight transposes (one launch)
    prep_all<<<PREP_XBLK + 6912, 256>>>(
        (const float4*)x, (__half2*)xh,
        Wq, Wqh, Wk, Wkh, Wv, Wvh, Wo, Woh, W1, W1h, W2, W2h);

    // merged Q/K/V projections (fp16 out)
    dense_h<<<dim3(DD/128, MM/128, 3), 256, DENSE_SMEM>>>(
        xh, Wqh, bq, Qh, nullptr, Wkh, bk, Kh, nullptr, Wvh, bv, Vh, nullptr,
        DD, DD, 0, 0);

    // per-head V transpose [seq][dk] -> [dk][seq]
    v_transpose<<<dim3(SS/64, BB*HH), dim3(64, 4)>>>(Vh, Vth);

    // softmax exp-sum partials (no max shift; scores O(1))
    stats_h<<<dim3(SS/128, SS/128, BB*HH), 256>>>(Qh, Kh, psp);
    rowstats<<<(BB*HH*SS + 255) / 256, 256>>>(psp, rip);

    // recompute S, write attn (fp32) once, ctx = P @ V (fp16)
    attn_pv_h<<<dim3(SS/128, BB*HH), 256, APV_SMEM>>>(Qh, Kh, Vth, rip, attn, ctxh);

    // attn_out = ctx @ Wo (split-K=2 partials, bias deferred to LN)
    dense_h<<<dim3(DD/128, MM/128, 2), 256, DENSE_SMEM>>>(
        ctxh, Woh, nullptr, nullptr, T2p, Woh, nullptr, nullptr, T2bp,
        nullptr, nullptr, nullptr, nullptr, DD, DD, 0, 1);

    // x1 = LN(x + p1 + p2 + bo) -> fp32 + fp16
    add_ln2_kernel<<<MM, 256>>>(x, T2p, T2bp, bo, g1, be1, X1p, x1h);

    // ff = relu(x1 @ W1 + b1) fp16
    dense_h<<<dim3(DFF/128, MM/128, 1), 256, DENSE_SMEM>>>(
        x1h, W1h, b1, ffh, nullptr, nullptr, nullptr, nullptr, nullptr,
        nullptr, nullptr, nullptr, nullptr, DD, DFF, 1, 0);

    // ff2 = ff @ W2 (split-K=2 partials, bias deferred to LN)
    dense_h<<<dim3(DD/128, MM/128, 2), 256, DENSE_SMEM>>>(
        ffh, W2h, nullptr, nullptr, T2p, W2h, nullptr, nullptr, T2bp,
        nullptr, nullptr, nullptr, nullptr, DFF, DD, 0, 1);

    // x2 = LN(x1 + p1 + p2 + b2) -> output
    add_ln2_kernel<<<MM, 256>>>(X1p, T2p, T2bp, b2, g2, be2, out, nullptr);
}